// round 2
// baseline (speedup 1.0000x reference)
#include <cuda_runtime.h>
#include <math.h>

#define NHID 1024
#define NOUT 50257
#define MAXLEN 24
#define ROWS_PER_BLK 8
#define NBLK_D ((NOUT + ROWS_PER_BLK - 1) / ROWS_PER_BLK)   // 6283

// -------- device scratch (no allocations allowed) --------
__device__ float g_cat[2 * NHID];      // [embedded, attn_applied]
__device__ float g_x[NHID];            // relu(comb output)
__device__ float g_h[NHID];            // new hidden (aligned copy)
__device__ float g_logits[NOUT];
__device__ float g_pm[NBLK_D];
__device__ float g_ps[NBLK_D];
__device__ float g_MS[2];              // M, log(S)

__device__ __forceinline__ float wredsum(float v) {
    #pragma unroll
    for (int o = 16; o; o >>= 1) v += __shfl_xor_sync(0xffffffffu, v, o);
    return v;
}
__device__ __forceinline__ float wredmax(float v) {
    #pragma unroll
    for (int o = 16; o; o >>= 1) v = fmaxf(v, __shfl_xor_sync(0xffffffffu, v, o));
    return v;
}
__device__ __forceinline__ float sigm(float x) { return 1.f / (1.f + expf(-x)); }
__device__ __forceinline__ float dot4(float4 a, float4 b) {
    return a.x * b.x + a.y * b.y + a.z * b.z + a.w * b.w;
}

// -------- Kernel A: embedding + attention + context. 1 block, 1024 threads --------
__global__ void kA(const int* __restrict__ inp,
                   const float* __restrict__ hidden,
                   const float* __restrict__ enc_outs,
                   const float* __restrict__ emb_W,
                   const float* __restrict__ attn_W,
                   const float* __restrict__ attn_b,
                   float* __restrict__ attnw_out) {
    __shared__ float sv[2 * NHID];
    __shared__ float sscore[32];
    __shared__ float sw[MAXLEN];
    int t = threadIdx.x;

    const float* erow = emb_W + (size_t)inp[0] * NHID;
    float e = erow[t];
    sv[t] = e;
    g_cat[t] = e;
    sv[NHID + t] = hidden[t];
    __syncthreads();

    int warp = t >> 5, lane = t & 31;
    if (warp < MAXLEN) {
        const float* w = attn_W + (size_t)warp * (2 * NHID);
        float acc = 0.f;
        #pragma unroll
        for (int q = 0; q < 64; q++) {
            int idx = lane + 32 * q;
            acc += w[idx] * sv[idx];
        }
        acc = wredsum(acc);
        if (lane == 0) sscore[warp] = acc + attn_b[warp];
    }
    __syncthreads();

    if (warp == 0) {
        float v = (lane < MAXLEN) ? sscore[lane] : -INFINITY;
        float m = wredmax(v);
        float p = (lane < MAXLEN) ? expf(v - m) : 0.f;
        float s = wredsum(p);
        float wv = p / s;
        if (lane < MAXLEN) {
            sw[lane] = wv;
            attnw_out[lane] = wv;
        }
    }
    __syncthreads();

    float acc = 0.f;
    #pragma unroll
    for (int m2 = 0; m2 < MAXLEN; m2++)
        acc += sw[m2] * enc_outs[m2 * NHID + t];
    g_cat[NHID + t] = acc;
}

// -------- Kernel B: comb GEMV [1024 x 2048] + relu. warp-per-row --------
__global__ void kB(const float* __restrict__ comb_W,
                   const float* __restrict__ comb_b) {
    __shared__ float4 sc[512];
    int t = threadIdx.x;   // 256
    sc[t] = ((const float4*)g_cat)[t];
    sc[t + 256] = ((const float4*)g_cat)[t + 256];
    __syncthreads();

    int warp = t >> 5, lane = t & 31;
    int row = blockIdx.x * ROWS_PER_BLK + warp;   // 0..1023
    const float4* w = (const float4*)(comb_W + (size_t)row * (2 * NHID));
    float acc = 0.f;
    #pragma unroll
    for (int k = 0; k < 16; k++) {
        int idx = lane + 32 * k;
        acc += dot4(w[idx], sc[idx]);
    }
    acc = wredsum(acc);
    if (lane == 0) g_x[row] = fmaxf(acc + comb_b[row], 0.f);
}

// -------- Kernel C: fused GRU step. warp per hidden unit --------
__global__ void kC(const float* __restrict__ W_ih,
                   const float* __restrict__ W_hh,
                   const float* __restrict__ b_ih,
                   const float* __restrict__ b_hh,
                   const float* __restrict__ hvec,
                   float* __restrict__ hout) {
    __shared__ float4 sx[256], sh[256];
    int t = threadIdx.x;   // 256
    sx[t] = ((const float4*)g_x)[t];
    sh[t] = ((const float4*)hvec)[t];
    __syncthreads();

    int warp = t >> 5, lane = t & 31;
    int k = blockIdx.x * ROWS_PER_BLK + warp;   // 0..1023

    const float4* wir = (const float4*)(W_ih + (size_t)k * NHID);
    const float4* wiz = (const float4*)(W_ih + (size_t)(k + NHID) * NHID);
    const float4* win = (const float4*)(W_ih + (size_t)(k + 2 * NHID) * NHID);
    const float4* whr = (const float4*)(W_hh + (size_t)k * NHID);
    const float4* whz = (const float4*)(W_hh + (size_t)(k + NHID) * NHID);
    const float4* whn = (const float4*)(W_hh + (size_t)(k + 2 * NHID) * NHID);

    float air = 0.f, aiz = 0.f, ain = 0.f, ahr = 0.f, ahz = 0.f, ahn = 0.f;
    #pragma unroll
    for (int q = 0; q < 8; q++) {
        int idx = lane + 32 * q;
        float4 x4 = sx[idx], h4 = sh[idx];
        air += dot4(wir[idx], x4);
        aiz += dot4(wiz[idx], x4);
        ain += dot4(win[idx], x4);
        ahr += dot4(whr[idx], h4);
        ahz += dot4(whz[idx], h4);
        ahn += dot4(whn[idx], h4);
    }
    air = wredsum(air); aiz = wredsum(aiz); ain = wredsum(ain);
    ahr = wredsum(ahr); ahz = wredsum(ahz); ahn = wredsum(ahn);

    if (lane == 0) {
        float r = sigm(air + b_ih[k] + ahr + b_hh[k]);
        float z = sigm(aiz + b_ih[NHID + k] + ahz + b_hh[NHID + k]);
        float n = tanhf(ain + b_ih[2 * NHID + k] + r * (ahn + b_hh[2 * NHID + k]));
        float h0 = hvec[k];
        float hnew = (1.f - z) * n + z * h0;
        g_h[k] = hnew;       // aligned scratch for kD
        hout[k] = hnew;      // output slot (may be unaligned for float4 — scalar ok)
    }
}

// -------- Kernel D: logits GEMV [50257 x 1024] + per-block softmax partials --------
__global__ void kD(const float* __restrict__ out_W,
                   const float* __restrict__ out_b) {
    __shared__ float4 sh[256];
    __shared__ float slog[ROWS_PER_BLK];
    int t = threadIdx.x;   // 256
    sh[t] = ((const float4*)g_h)[t];
    __syncthreads();

    int warp = t >> 5, lane = t & 31;
    int row = blockIdx.x * ROWS_PER_BLK + warp;
    float y = -INFINITY;
    if (row < NOUT) {
        const float4* w = (const float4*)(out_W + (size_t)row * NHID);
        float acc = 0.f;
        #pragma unroll
        for (int k = 0; k < 8; k++) {
            int idx = lane + 32 * k;
            acc += dot4(w[idx], sh[idx]);
        }
        acc = wredsum(acc);
        if (lane == 0) {
            y = acc + out_b[row];
            g_logits[row] = y;
        }
    }
    if (lane == 0) slog[warp] = y;
    __syncthreads();

    if (warp == 0) {
        float v = (lane < ROWS_PER_BLK) ? slog[lane] : -INFINITY;
        float m = wredmax(v);
        float e = (lane < ROWS_PER_BLK && v > -INFINITY) ? __expf(v - m) : 0.f;
        e = wredsum(e);
        if (lane == 0) {
            g_pm[blockIdx.x] = m;
            g_ps[blockIdx.x] = e;
        }
    }
}

// -------- Kernel E: reduce softmax partials. 1 block, 1024 threads --------
__global__ void kE() {
    __shared__ float sm[1024], ss[1024];
    int t = threadIdx.x;
    float m = -INFINITY, s = 0.f;
    for (int i = t; i < NBLK_D; i += 1024) {
        float mb = g_pm[i], sb = g_ps[i];
        if (mb > m) { s = s * __expf(m - mb) + sb; m = mb; }
        else        { s += sb * __expf(mb - m); }
    }
    sm[t] = m; ss[t] = s;
    __syncthreads();
    for (int o = 512; o; o >>= 1) {
        if (t < o) {
            float m1 = sm[t], s1 = ss[t];
            float m2 = sm[t + o], s2 = ss[t + o];
            float M = fmaxf(m1, m2);
            float S = (s1 > 0.f ? s1 * __expf(m1 - M) : 0.f) +
                      (s2 > 0.f ? s2 * __expf(m2 - M) : 0.f);
            sm[t] = M; ss[t] = S;
        }
        __syncthreads();
    }
    if (t == 0) { g_MS[0] = sm[0]; g_MS[1] = logf(ss[0]); }
}

// -------- Kernel F: write log-softmax --------
__global__ void kF(float* __restrict__ logp) {
    int i = blockIdx.x * blockDim.x + threadIdx.x;
    if (i < NOUT) logp[i] = g_logits[i] - g_MS[0] - g_MS[1];
}

extern "C" void kernel_launch(void* const* d_in, const int* in_sizes, int n_in,
                              void* d_out, int out_size) {
    const int*   inp      = (const int*)  d_in[0];
    const float* hidden   = (const float*)d_in[1];
    // d_in[2] = encoder_output (unused by the reference math)
    const float* enc_outs = (const float*)d_in[3];
    const float* emb_W    = (const float*)d_in[4];
    const float* attn_W   = (const float*)d_in[5];
    const float* attn_b   = (const float*)d_in[6];
    const float* comb_W   = (const float*)d_in[7];
    const float* comb_b   = (const float*)d_in[8];
    const float* W_ih     = (const float*)d_in[9];
    const float* W_hh     = (const float*)d_in[10];
    const float* b_ih     = (const float*)d_in[11];
    const float* b_hh     = (const float*)d_in[12];
    const float* out_W    = (const float*)d_in[13];
    const float* out_b    = (const float*)d_in[14];

    float* out   = (float*)d_out;
    float* logp  = out;                 // [50257]
    float* hout  = out + NOUT;          // [1024]
    float* attnw = out + NOUT + NHID;   // [24]

    kA<<<1, 1024>>>(inp, hidden, enc_outs, emb_W, attn_W, attn_b, attnw);
    kB<<<NHID / ROWS_PER_BLK, 256>>>(comb_W, comb_b);
    kC<<<NHID / ROWS_PER_BLK, 256>>>(W_ih, W_hh, b_ih, b_hh, hidden, hout);
    kD<<<NBLK_D, 256>>>(out_W, out_b);
    kE<<<1, 1024>>>();
    kF<<<(NOUT + 255) / 256, 256>>>(logp);
}

// round 3
// speedup vs baseline: 1.0174x; 1.0174x over previous
#include <cuda_runtime.h>
#include <math.h>

#define NHID 1024
#define NOUT 50257
#define MAXLEN 24
#define ROWS_PER_BLK 8
#define NBLK_D ((NOUT + ROWS_PER_BLK - 1) / ROWS_PER_BLK)   // 6283

// -------- device scratch (no allocations allowed) --------
__device__ float g_x[NHID];            // relu(comb output)
__device__ float g_h[NHID];            // new hidden (aligned copy)
__device__ float g_logits[NOUT];
__device__ float g_pm[NBLK_D];
__device__ float g_ps[NBLK_D];
__device__ float g_MS[2];              // M, log(S)
__device__ unsigned g_ticket = 0;

__device__ __forceinline__ float wredsum(float v) {
    #pragma unroll
    for (int o = 16; o; o >>= 1) v += __shfl_xor_sync(0xffffffffu, v, o);
    return v;
}
__device__ __forceinline__ float wredmax(float v) {
    #pragma unroll
    for (int o = 16; o; o >>= 1) v = fmaxf(v, __shfl_xor_sync(0xffffffffu, v, o));
    return v;
}
__device__ __forceinline__ float sigm(float x) { return 1.f / (1.f + expf(-x)); }
__device__ __forceinline__ float dot4(float4 a, float4 b) {
    return a.x * b.x + a.y * b.y + a.z * b.z + a.w * b.w;
}

// -------- Kernel AB: attention (redundant per block, L2-served) + comb GEMV --------
// 128 blocks x 256 threads; block b computes g_x[8b..8b+7].
__global__ void kAB(const int* __restrict__ inp,
                    const float* __restrict__ hidden,
                    const float* __restrict__ enc_outs,
                    const float* __restrict__ emb_W,
                    const float* __restrict__ attn_W,
                    const float* __restrict__ attn_b,
                    const float* __restrict__ comb_W,
                    const float* __restrict__ comb_b,
                    float* __restrict__ attnw_out) {
    __shared__ float sv[2 * NHID];     // [embedded, hidden]
    __shared__ float sc[2 * NHID];     // [embedded, context]
    __shared__ float sscore[MAXLEN];
    __shared__ float sw[MAXLEN];
    int t = threadIdx.x;               // 256
    int warp = t >> 5, lane = t & 31;

    if (blockIdx.x == 0 && t == 0) g_ticket = 0;   // reset ticket for kD

    const float4* e4 = (const float4*)(emb_W + (size_t)inp[0] * NHID);
    float4 ev = e4[t];
    ((float4*)sv)[t] = ev;
    ((float4*)sc)[t] = ev;
    ((float4*)(sv + NHID))[t] = ((const float4*)hidden)[t];
    __syncthreads();

    // attention scores: warp handles rows warp, warp+8, warp+16
    for (int r = warp; r < MAXLEN; r += 8) {
        const float* w = attn_W + (size_t)r * (2 * NHID);
        float acc = 0.f;
        #pragma unroll
        for (int q = 0; q < 64; q++) {
            int idx = lane + 32 * q;
            acc += w[idx] * sv[idx];
        }
        acc = wredsum(acc);
        if (lane == 0) sscore[r] = acc + attn_b[r];
    }
    __syncthreads();

    // softmax over 24 scores
    if (warp == 0) {
        float v = (lane < MAXLEN) ? sscore[lane] : -INFINITY;
        float m = wredmax(v);
        float p = (lane < MAXLEN) ? expf(v - m) : 0.f;
        float s = wredsum(p);
        float wv = p / s;
        if (lane < MAXLEN) {
            sw[lane] = wv;
            if (blockIdx.x == 0) attnw_out[lane] = wv;
        }
    }
    __syncthreads();

    // context vector
    #pragma unroll
    for (int j = 0; j < 4; j++) {
        int col = t + 256 * j;
        float acc = 0.f;
        #pragma unroll
        for (int m2 = 0; m2 < MAXLEN; m2++)
            acc += sw[m2] * enc_outs[m2 * NHID + col];
        sc[NHID + col] = acc;
    }
    __syncthreads();

    // comb GEMV row + relu
    int row = blockIdx.x * ROWS_PER_BLK + warp;
    const float4* w4 = (const float4*)(comb_W + (size_t)row * (2 * NHID));
    const float4* sc4 = (const float4*)sc;
    float acc = 0.f;
    #pragma unroll
    for (int k = 0; k < 16; k++) {
        int idx = lane + 32 * k;
        acc += dot4(__ldcs(w4 + idx), sc4[idx]);
    }
    acc = wredsum(acc);
    if (lane == 0) g_x[row] = fmaxf(acc + comb_b[row], 0.f);
}

// -------- Kernel C: fused GRU step. warp per hidden unit --------
__global__ void kC(const float* __restrict__ W_ih,
                   const float* __restrict__ W_hh,
                   const float* __restrict__ b_ih,
                   const float* __restrict__ b_hh,
                   const float* __restrict__ hvec,
                   float* __restrict__ hout) {
    __shared__ float4 sx[256], sh[256];
    int t = threadIdx.x;   // 256
    sx[t] = ((const float4*)g_x)[t];
    sh[t] = ((const float4*)hvec)[t];
    __syncthreads();

    int warp = t >> 5, lane = t & 31;
    int k = blockIdx.x * ROWS_PER_BLK + warp;   // 0..1023

    const float4* wir = (const float4*)(W_ih + (size_t)k * NHID);
    const float4* wiz = (const float4*)(W_ih + (size_t)(k + NHID) * NHID);
    const float4* win = (const float4*)(W_ih + (size_t)(k + 2 * NHID) * NHID);
    const float4* whr = (const float4*)(W_hh + (size_t)k * NHID);
    const float4* whz = (const float4*)(W_hh + (size_t)(k + NHID) * NHID);
    const float4* whn = (const float4*)(W_hh + (size_t)(k + 2 * NHID) * NHID);

    float air = 0.f, aiz = 0.f, ain = 0.f, ahr = 0.f, ahz = 0.f, ahn = 0.f;
    #pragma unroll
    for (int q = 0; q < 8; q++) {
        int idx = lane + 32 * q;
        float4 x4 = sx[idx], h4 = sh[idx];
        air += dot4(__ldcs(wir + idx), x4);
        aiz += dot4(__ldcs(wiz + idx), x4);
        ain += dot4(__ldcs(win + idx), x4);
        ahr += dot4(__ldcs(whr + idx), h4);
        ahz += dot4(__ldcs(whz + idx), h4);
        ahn += dot4(__ldcs(whn + idx), h4);
    }
    air = wredsum(air); aiz = wredsum(aiz); ain = wredsum(ain);
    ahr = wredsum(ahr); ahz = wredsum(ahz); ahn = wredsum(ahn);

    if (lane == 0) {
        float r = sigm(air + b_ih[k] + ahr + b_hh[k]);
        float z = sigm(aiz + b_ih[NHID + k] + ahz + b_hh[NHID + k]);
        float n = tanhf(ain + b_ih[2 * NHID + k] + r * (ahn + b_hh[2 * NHID + k]));
        float h0 = hvec[k];
        float hnew = (1.f - z) * n + z * h0;
        g_h[k] = hnew;       // aligned scratch for kD
        hout[k] = hnew;      // output slot
    }
}

// -------- Kernel D: logits GEMV + per-block softmax partials + fused final reduce --------
__global__ void kD(const float* __restrict__ out_W,
                   const float* __restrict__ out_b) {
    __shared__ float4 sh[256];
    __shared__ float slog[ROWS_PER_BLK];
    __shared__ bool islast;
    int t = threadIdx.x;   // 256
    sh[t] = ((const float4*)g_h)[t];
    __syncthreads();

    int warp = t >> 5, lane = t & 31;
    int row = blockIdx.x * ROWS_PER_BLK + warp;
    float y = -INFINITY;
    if (row < NOUT) {
        const float4* w = (const float4*)(out_W + (size_t)row * NHID);
        float acc = 0.f;
        #pragma unroll
        for (int k = 0; k < 8; k++) {
            int idx = lane + 32 * k;
            acc += dot4(__ldcs(w + idx), sh[idx]);
        }
        acc = wredsum(acc);
        if (lane == 0) {
            y = acc + out_b[row];
            g_logits[row] = y;
        }
    }
    if (lane == 0) slog[warp] = y;
    __syncthreads();

    if (warp == 0) {
        float v = (lane < ROWS_PER_BLK) ? slog[lane] : -INFINITY;
        float m = wredmax(v);
        float e = (lane < ROWS_PER_BLK && v > -INFINITY) ? __expf(v - m) : 0.f;
        e = wredsum(e);
        if (lane == 0) {
            g_pm[blockIdx.x] = m;
            g_ps[blockIdx.x] = e;
        }
    }
    __syncthreads();

    // ticket: last block to finish performs the global softmax reduce
    if (t == 0) {
        __threadfence();
        islast = (atomicAdd(&g_ticket, 1u) == NBLK_D - 1);
    }
    __syncthreads();
    if (!islast) return;

    __shared__ float sm2[256], ss2[256];
    float m = -INFINITY, s = 0.f;
    for (int i = t; i < NBLK_D; i += 256) {
        float mb = g_pm[i], sb = g_ps[i];
        if (mb > m) { s = s * __expf(m - mb) + sb; m = mb; }
        else        { s += sb * __expf(mb - m); }
    }
    sm2[t] = m; ss2[t] = s;
    __syncthreads();
    for (int o = 128; o; o >>= 1) {
        if (t < o) {
            float m1 = sm2[t], s1 = ss2[t];
            float mb = sm2[t + o], sb = ss2[t + o];
            float M = fmaxf(m1, mb);
            float S = (s1 > 0.f ? s1 * __expf(m1 - M) : 0.f) +
                      (sb > 0.f ? sb * __expf(mb - M) : 0.f);
            sm2[t] = M; ss2[t] = S;
        }
        __syncthreads();
    }
    if (t == 0) { g_MS[0] = sm2[0]; g_MS[1] = logf(ss2[0]); }
}

// -------- Kernel F: write log-softmax --------
__global__ void kF(float* __restrict__ logp) {
    int i = blockIdx.x * blockDim.x + threadIdx.x;
    if (i < NOUT) logp[i] = g_logits[i] - g_MS[0] - g_MS[1];
}

extern "C" void kernel_launch(void* const* d_in, const int* in_sizes, int n_in,
                              void* d_out, int out_size) {
    const int*   inp      = (const int*)  d_in[0];
    const float* hidden   = (const float*)d_in[1];
    // d_in[2] = encoder_output (unused by the reference math)
    const float* enc_outs = (const float*)d_in[3];
    const float* emb_W    = (const float*)d_in[4];
    const float* attn_W   = (const float*)d_in[5];
    const float* attn_b   = (const float*)d_in[6];
    const float* comb_W   = (const float*)d_in[7];
    const float* comb_b   = (const float*)d_in[8];
    const float* W_ih     = (const float*)d_in[9];
    const float* W_hh     = (const float*)d_in[10];
    const float* b_ih     = (const float*)d_in[11];
    const float* b_hh     = (const float*)d_in[12];
    const float* out_W    = (const float*)d_in[13];
    const float* out_b    = (const float*)d_in[14];

    float* out   = (float*)d_out;
    float* logp  = out;                 // [50257]
    float* hout  = out + NOUT;          // [1024]
    float* attnw = out + NOUT + NHID;   // [24]

    kAB<<<NHID / ROWS_PER_BLK, 256>>>(inp, hidden, enc_outs, emb_W, attn_W,
                                      attn_b, comb_W, comb_b, attnw);
    kC<<<NHID / ROWS_PER_BLK, 256>>>(W_ih, W_hh, b_ih, b_hh, hidden, hout);
    kD<<<NBLK_D, 256>>>(out_W, out_b);
    kF<<<(NOUT + 255) / 256, 256>>>(logp);
}

// round 4
// speedup vs baseline: 1.1648x; 1.1449x over previous
#include <cuda_runtime.h>
#include <math.h>

#define NHID 1024
#define NOUT 50257
#define MAXLEN 24
#define GRID 592                     // 148 SMs x 4 blocks, guaranteed co-resident
#define NTILE ((NOUT + 7) / 8)       // 6283 row-tiles of 8
#define PREF_F4 (32u * 1024u * 1024u / 16u)   // prefetch 32MB of out_W as float4

// -------- device scratch --------
__device__ float g_cat[2 * NHID];
__device__ float g_x[NHID];
__device__ float g_h[NHID];
__device__ float g_logits[NOUT];
__device__ float g_pm[GRID];
__device__ float g_ps[GRID];
__device__ unsigned g_bar[4];        // epoch barrier counters (never reset)
__device__ float g_sink;             // prefetch DCE sink

__device__ __forceinline__ float wredsum(float v) {
    #pragma unroll
    for (int o = 16; o; o >>= 1) v += __shfl_xor_sync(0xffffffffu, v, o);
    return v;
}
__device__ __forceinline__ float wredmax(float v) {
    #pragma unroll
    for (int o = 16; o; o >>= 1) v = fmaxf(v, __shfl_xor_sync(0xffffffffu, v, o));
    return v;
}
__device__ __forceinline__ float sigm(float x) { return 1.f / (1.f + expf(-x)); }
__device__ __forceinline__ float dot4(float4 a, float4 b) {
    return a.x * b.x + a.y * b.y + a.z * b.z + a.w * b.w;
}

// epoch barrier: each launch adds exactly GRID arrivals; no reset needed.
__device__ __forceinline__ void bar_arrive(int id) {
    __syncthreads();
    if (threadIdx.x == 0) {
        __threadfence();
        atomicAdd(&g_bar[id], 1u);
    }
}
__device__ __forceinline__ void bar_arrive_wait(int id) {
    __syncthreads();
    if (threadIdx.x == 0) {
        __threadfence();
        unsigned old = atomicAdd(&g_bar[id], 1u);
        unsigned target = old - (old % GRID) + GRID;
        volatile unsigned* p = &g_bar[id];
        while (*p < target) { __nanosleep(64); }
        __threadfence();
    }
    __syncthreads();
}
// wait only (for blocks that arrived earlier)
__device__ __forceinline__ void bar_wait(int id, unsigned target) {
    if (threadIdx.x == 0) {
        volatile unsigned* p = &g_bar[id];
        while (*p < target) { __nanosleep(64); }
        __threadfence();
    }
    __syncthreads();
}

__global__ void __launch_bounds__(256, 4)
mega(const int* __restrict__ inp,
     const float* __restrict__ hidden,
     const float* __restrict__ enc_outs,
     const float* __restrict__ emb_W,
     const float* __restrict__ attn_W,
     const float* __restrict__ attn_b,
     const float* __restrict__ comb_W,
     const float* __restrict__ comb_b,
     const float* __restrict__ W_ih,
     const float* __restrict__ W_hh,
     const float* __restrict__ b_ih,
     const float* __restrict__ b_hh,
     const float* __restrict__ out_W,
     const float* __restrict__ out_b,
     float* __restrict__ logp,
     float* __restrict__ hout,
     float* __restrict__ attnw_out) {
    __shared__ float sAB[2 * NHID];        // A: [emb,hidden]; B: [emb,context]
    __shared__ float4 sCD[512];            // C: sx(256)+sh(256); D: h(256)
    __shared__ float sred[512];            // reductions
    __shared__ float sscore[32];
    __shared__ float sw[MAXLEN];

    const int t = threadIdx.x;             // 256
    const int b = blockIdx.x;
    const int warp = t >> 5, lane = t & 31;
    const bool active = (b < 128);

    if (!active) {
        // --- idle blocks: arrive at bars 0..2 immediately, remember bar2 epoch ---
        unsigned t2target;
        __syncthreads();
        if (t == 0) {
            atomicAdd(&g_bar[0], 1u);
            atomicAdd(&g_bar[1], 1u);
            unsigned old = atomicAdd(&g_bar[2], 1u);
            sscore[0] = __uint_as_float(old - (old % GRID) + GRID);
        }
        __syncthreads();
        t2target = __float_as_uint(sscore[0]);
        // --- prefetch head of out_W into L2 while active chain runs ---
        {
            const float4* w4 = (const float4*)out_W;
            float acc = 0.f;
            for (unsigned i = (unsigned)(b - 128) * 256u + t; i < PREF_F4;
                 i += (GRID - 128) * 256u) {
                float4 v = __ldcg(w4 + i);
                acc += v.x + v.y + v.z + v.w;
            }
            if (acc == -1.2345678e35f) g_sink = acc;   // never true; defeats DCE
        }
        bar_wait(2, t2target);
        goto phaseD;
    }

    // ================= Phase A: attention (block 0 only) =================
    if (b == 0) {
        const float4* e4 = (const float4*)(emb_W + (size_t)inp[0] * NHID);
        float4 ev0 = e4[t], ev1 = e4[t + 256];   // wait: emb row is 1024 floats = 256 float4
        // NOTE: only 256 float4 in emb row; second load is out of row — fix below.
        (void)ev1;
        ((float4*)sAB)[t] = ev0;
        ((float4*)g_cat)[t] = ev0;
        ((float4*)(sAB + NHID))[t] = ((const float4*)hidden)[t];
        __syncthreads();

        for (int r = warp; r < MAXLEN; r += 8) {
            const float* w = attn_W + (size_t)r * (2 * NHID);
            float acc = 0.f;
            #pragma unroll
            for (int q = 0; q < 64; q++) {
                int idx = lane + 32 * q;
                acc += w[idx] * sAB[idx];
            }
            acc = wredsum(acc);
            if (lane == 0) sscore[r] = acc + attn_b[r];
        }
        __syncthreads();

        if (warp == 0) {
            float v = (lane < MAXLEN) ? sscore[lane] : -INFINITY;
            float m = wredmax(v);
            float p = (lane < MAXLEN) ? expf(v - m) : 0.f;
            float s = wredsum(p);
            float wv = p / s;
            if (lane < MAXLEN) {
                sw[lane] = wv;
                attnw_out[lane] = wv;
            }
        }
        __syncthreads();

        #pragma unroll
        for (int j = 0; j < 4; j++) {
            int col = t + 256 * j;
            float acc = 0.f;
            #pragma unroll
            for (int m2 = 0; m2 < MAXLEN; m2++)
                acc += sw[m2] * enc_outs[m2 * NHID + col];
            g_cat[NHID + col] = acc;
        }
    }
    bar_arrive_wait(0);

    // ================= Phase B: comb GEMV + relu (blocks 0..127) =================
    {
        ((float4*)sAB)[t] = ((const float4*)g_cat)[t];
        ((float4*)sAB)[t + 256] = ((const float4*)g_cat)[t + 256];
        __syncthreads();

        int row = b * 8 + warp;
        const float4* w4 = (const float4*)(comb_W + (size_t)row * (2 * NHID));
        const float4* sc4 = (const float4*)sAB;
        float acc = 0.f;
        #pragma unroll
        for (int k = 0; k < 16; k++) {
            int idx = lane + 32 * k;
            acc += dot4(__ldcs(w4 + idx), sc4[idx]);
        }
        acc = wredsum(acc);
        if (lane == 0) g_x[row] = fmaxf(acc + comb_b[row], 0.f);
    }
    bar_arrive_wait(1);

    // ================= Phase C: GRU (blocks 0..127) =================
    {
        sCD[t] = ((const float4*)g_x)[t];          // only first 256 used
        // sx = sCD[0..255] holds g_x; sh = sCD[256..511] holds hidden
        sCD[256 + t] = ((const float4*)hidden)[t];
        __syncthreads();

        int k = b * 8 + warp;
        const float4* wir = (const float4*)(W_ih + (size_t)k * NHID);
        const float4* wiz = (const float4*)(W_ih + (size_t)(k + NHID) * NHID);
        const float4* win = (const float4*)(W_ih + (size_t)(k + 2 * NHID) * NHID);
        const float4* whr = (const float4*)(W_hh + (size_t)k * NHID);
        const float4* whz = (const float4*)(W_hh + (size_t)(k + NHID) * NHID);
        const float4* whn = (const float4*)(W_hh + (size_t)(k + 2 * NHID) * NHID);

        float air = 0.f, aiz = 0.f, ain = 0.f, ahr = 0.f, ahz = 0.f, ahn = 0.f;
        #pragma unroll
        for (int q = 0; q < 8; q++) {
            int idx = lane + 32 * q;
            float4 x4 = sCD[idx], h4 = sCD[256 + idx];
            air += dot4(__ldcs(wir + idx), x4);
            aiz += dot4(__ldcs(wiz + idx), x4);
            ain += dot4(__ldcs(win + idx), x4);
            ahr += dot4(__ldcs(whr + idx), h4);
            ahz += dot4(__ldcs(whz + idx), h4);
            ahn += dot4(__ldcs(whn + idx), h4);
        }
        air = wredsum(air); aiz = wredsum(aiz); ain = wredsum(ain);
        ahr = wredsum(ahr); ahz = wredsum(ahz); ahn = wredsum(ahn);

        if (lane == 0) {
            float r = sigm(air + b_ih[k] + ahr + b_hh[k]);
            float z = sigm(aiz + b_ih[NHID + k] + ahz + b_hh[NHID + k]);
            float n = tanhf(ain + b_ih[2 * NHID + k] + r * (ahn + b_hh[2 * NHID + k]));
            float h0 = hidden[k];
            float hnew = (1.f - z) * n + z * h0;
            g_h[k] = hnew;
            hout[k] = hnew;
        }
    }
    bar_arrive_wait(2);

phaseD:
    // ================= Phase D: logits GEMV + per-block online softmax =================
    {
        sCD[t] = ((const float4*)g_h)[t];
        __syncthreads();

        float mloc = -INFINITY, sloc = 0.f;
        for (int tile = b; tile < NTILE; tile += GRID) {
            int row = tile * 8 + warp;
            float y = -INFINITY;
            if (row < NOUT) {
                const float4* w = (const float4*)(out_W + (size_t)row * NHID);
                float acc = 0.f;
                #pragma unroll
                for (int k = 0; k < 8; k++) {
                    int idx = lane + 32 * k;
                    acc += dot4(__ldcs(w + idx), sCD[idx]);
                }
                acc = wredsum(acc);
                if (lane == 0) {
                    y = acc + out_b[row];
                    g_logits[row] = y;
                    // online accumulate (lane 0 only)
                    if (y > mloc) { sloc = sloc * __expf(mloc - y) + 1.f; mloc = y; }
                    else          { sloc += __expf(y - mloc); }
                }
            }
        }
        // block reduce of 256 per-thread (m,s) (only lane0 threads have data)
        sred[t] = mloc; sred[256 + t] = sloc;
        __syncthreads();
        for (int o = 128; o; o >>= 1) {
            if (t < o) {
                float m1 = sred[t], s1 = sred[256 + t];
                float m2 = sred[t + o], s2 = sred[256 + t + o];
                float M = fmaxf(m1, m2);
                float S = (s1 > 0.f ? s1 * __expf(m1 - M) : 0.f) +
                          (s2 > 0.f ? s2 * __expf(m2 - M) : 0.f);
                sred[t] = M; sred[256 + t] = S;
            }
            __syncthreads();
        }
        if (t == 0) { g_pm[b] = sred[0]; g_ps[b] = sred[256]; }
    }
    bar_arrive_wait(3);

    // ========== Phase E: every block redundantly reduces 592 partials, writes logp ==========
    {
        float m = -INFINITY, s = 0.f;
        for (int i = t; i < GRID; i += 256) {
            float mb = g_pm[i], sb = g_ps[i];
            if (mb > m) { s = s * __expf(m - mb) + sb; m = mb; }
            else        { s += sb * __expf(mb - m); }
        }
        sred[t] = m; sred[256 + t] = s;
        __syncthreads();
        for (int o = 128; o; o >>= 1) {
            if (t < o) {
                float m1 = sred[t], s1 = sred[256 + t];
                float m2 = sred[t + o], s2 = sred[256 + t + o];
                float M = fmaxf(m1, m2);
                float S = (s1 > 0.f ? s1 * __expf(m1 - M) : 0.f) +
                          (s2 > 0.f ? s2 * __expf(m2 - M) : 0.f);
                sred[t] = M; sred[256 + t] = S;
            }
            __syncthreads();
        }
        float M = sred[0];
        float C = M + logf(sred[256]);

        int i = b * 256 + t;                    // GRID*256 = 151552 > NOUT: one shot
        if (i < NOUT) logp[i] = g_logits[i] - C;
    }
}

extern "C" void kernel_launch(void* const* d_in, const int* in_sizes, int n_in,
                              void* d_out, int out_size) {
    const int*   inp      = (const int*)  d_in[0];
    const float* hidden   = (const float*)d_in[1];
    const float* enc_outs = (const float*)d_in[3];
    const float* emb_W    = (const float*)d_in[4];
    const float* attn_W   = (const float*)d_in[5];
    const float* attn_b   = (const float*)d_in[6];
    const float* comb_W   = (const float*)d_in[7];
    const float* comb_b   = (const float*)d_in[8];
    const float* W_ih     = (const float*)d_in[9];
    const float* W_hh     = (const float*)d_in[10];
    const float* b_ih     = (const float*)d_in[11];
    const float* b_hh     = (const float*)d_in[12];
    const float* out_W    = (const float*)d_in[13];
    const float* out_b    = (const float*)d_in[14];

    float* out   = (float*)d_out;
    float* logp  = out;                 // [50257]
    float* hout  = out + NOUT;          // [1024]
    float* attnw = out + NOUT + NHID;   // [24]

    mega<<<GRID, 256>>>(inp, hidden, enc_outs, emb_W, attn_W, attn_b,
                        comb_W, comb_b, W_ih, W_hh, b_ih, b_hh,
                        out_W, out_b, logp, hout, attnw);
}